// round 2
// baseline (speedup 1.0000x reference)
#include <cuda_runtime.h>
#include <math.h>

#define BATCH 8
#define NPTS 2048
#define NTOT (BATCH*NPTS)
#define CH 128
#define KNN 16
#define HID 32
#define EPSV 1e-6f

typedef unsigned long long ull;

// ---------------- scratch (static device globals) ---------------------------
__device__ float g_Q[NTOT*CH*3];
__device__ float g_K[NTOT*CH*3];
__device__ float g_U[NTOT*CH*3];
__device__ float g_Wt[3*CH*CH];      // transposed weights, layout [w][c][o]
__device__ int   g_idx[NTOT*KNN];    // global neighbor index (b*NPTS + j)
__device__ float g_dist[NTOT*KNN];
__device__ float g_qn[NTOT];
__device__ float g_kn[NTOT];

// ---------------- packed f32x2 helpers (Blackwell FFMA2) --------------------
__device__ __forceinline__ ull pack2(float lo, float hi) {
    ull r;
    asm("mov.b64 %0, {%1,%2};" : "=l"(r) : "f"(lo), "f"(hi));
    return r;
}
__device__ __forceinline__ void unpack2(ull v, float& lo, float& hi) {
    asm("mov.b64 {%0,%1}, %2;" : "=f"(lo), "=f"(hi) : "l"(v));
}
__device__ __forceinline__ ull fma2(ull a, ull b, ull c) {
    ull d;
    asm("fma.rn.f32x2 %0, %1, %2, %3;" : "=l"(d) : "l"(a), "l"(b), "l"(c));
    return d;
}

// ---------------- weight transpose: W[o][c] -> Wt[c][o] ----------------------
__global__ void transpose_w_kernel(const float* __restrict__ Wq,
                                   const float* __restrict__ Wk,
                                   const float* __restrict__ Wu) {
    int i = blockIdx.x * 256 + threadIdx.x;       // i = o*128 + c
    if (i >= CH*CH) return;
    int o = i >> 7, c = i & 127;
    g_Wt[0*CH*CH + c*CH + o] = Wq[i];
    g_Wt[1*CH*CH + c*CH + o] = Wk[i];
    g_Wt[2*CH*CH + c*CH + o] = Wu[i];
}

// ---------------- KNN: warp per query, per-lane sorted top-16, warp merge ---
__global__ __launch_bounds__(256) void knn_kernel(const float* __restrict__ x) {
    __shared__ float sx[NPTS*3];   // 24 KB
    __shared__ float ssq[NPTS];    //  8 KB
    int b  = blockIdx.x >> 8;
    int n0 = (blockIdx.x & 255) << 3;
    const float* xb = x + (size_t)b * NPTS * 3;
    for (int i = threadIdx.x; i < NPTS*3; i += 256) sx[i] = xb[i];
    __syncthreads();
    for (int i = threadIdx.x; i < NPTS; i += 256) {
        float a = sx[3*i], bb = sx[3*i+1], c = sx[3*i+2];
        ssq[i] = a*a + bb*bb + c*c;
    }
    __syncthreads();

    int warp = threadIdx.x >> 5, lane = threadIdx.x & 31;
    int n = n0 + warp;
    float qx = sx[3*n], qy = sx[3*n+1], qz = sx[3*n+2];
    float qs = ssq[n];

    float bd[KNN]; int bi[KNN];
#pragma unroll
    for (int t = 0; t < KNN; t++) { bd[t] = INFINITY; bi[t] = 0x7fffffff; }

    for (int j = lane; j < NPTS; j += 32) {
        float dot = qx*sx[3*j] + qy*sx[3*j+1] + qz*sx[3*j+2];
        float d2 = (qs + ssq[j]) - 2.f*dot;      // same formula as reference, no clamp
        if (j == n) d2 = INFINITY;               // exclude self
        if (d2 < bd[KNN-1]) {
            bool placed = false;
#pragma unroll
            for (int t = KNN-1; t >= 1; t--) {
                if (!placed) {
                    if (d2 < bd[t-1]) { bd[t] = bd[t-1]; bi[t] = bi[t-1]; }
                    else              { bd[t] = d2;      bi[t] = j; placed = true; }
                }
            }
            if (!placed) { bd[0] = d2; bi[0] = j; }
        }
    }

    int myj = 0;
    for (int r = 0; r < KNN; r++) {
        ull key = (((ull)__float_as_uint(bd[0])) << 32) | (unsigned)bi[0];
        ull mn = key;
#pragma unroll
        for (int s = 16; s > 0; s >>= 1) {
            ull o = __shfl_xor_sync(0xffffffffu, mn, s);
            mn = (o < mn) ? o : mn;
        }
        if (lane == r) myj = (int)(unsigned)(mn & 0xffffffffu);
        if (key == mn) {
#pragma unroll
            for (int t = 0; t < KNN-1; t++) { bd[t] = bd[t+1]; bi[t] = bi[t+1]; }
            bd[KNN-1] = INFINITY; bi[KNN-1] = 0x7fffffff;
        }
    }

    if (lane < KNN) {
        int j = myj;
        float dx = qx - sx[3*j], dy = qy - sx[3*j+1], dz = qz - sx[3*j+2];
        int gi = ((b << 11) + n) * KNN + lane;
        g_idx[gi]  = (b << 11) + j;
        g_dist[gi] = sqrtf(dx*dx + dy*dy + dz*dz);
    }
}

// ---------------- fused GEMM (FFMA2 packed) + channel-norm reduction --------
// 8 points per block; shared v transposed to [c][coord][p] so point pairs pack.
__global__ __launch_bounds__(256) void gemm_kernel(const float* __restrict__ v) {
    __shared__ float svt[8*CH*3];            // [c][coord][8 points], 12 KB
    __shared__ float swn[2][4][4][2];        // [half][pt][warp4][q/k]
    int p0 = blockIdx.x << 3;
    const float* vb = v + (size_t)p0 * (CH*3);
    for (int i = threadIdx.x; i < 8*CH*3; i += 256) {
        int p = i / 384, r = i % 384;
        int c = r / 3, coord = r % 3;
        svt[c*24 + coord*8 + p] = vb[i];
    }
    __syncthreads();

    int o    = threadIdx.x & 127;
    int h    = threadIdx.x >> 7;       // half: points h*4..h*4+3
    int lane = threadIdx.x & 31;
    int w4   = (threadIdx.x >> 5) & 3;
    int h4   = h * 4;

    ull acc[2][3][3];                  // [pair][qku][coord]
#pragma unroll
    for (int pr = 0; pr < 2; pr++)
#pragma unroll
        for (int w = 0; w < 3; w++)
#pragma unroll
            for (int d = 0; d < 3; d++) acc[pr][w][d] = 0ULL;

    const float* wq = g_Wt + o;
    const float* wk = g_Wt + CH*CH + o;
    const float* wu = g_Wt + 2*CH*CH + o;

#pragma unroll 4
    for (int c = 0; c < CH; c++) {
        float aq = __ldg(wq + (c << 7));
        float ak = __ldg(wk + (c << 7));
        float au = __ldg(wu + (c << 7));
        ull aq2 = pack2(aq, aq), ak2 = pack2(ak, ak), au2 = pack2(au, au);
#pragma unroll
        for (int pr = 0; pr < 2; pr++) {
            const ull* vp = reinterpret_cast<const ull*>(&svt[c*24 + h4 + pr*2]);
            ull vx = vp[0];   // coord 0
            ull vy = vp[4];   // coord 1 (+8 floats)
            ull vz = vp[8];   // coord 2 (+16 floats)
            acc[pr][0][0] = fma2(aq2, vx, acc[pr][0][0]);
            acc[pr][0][1] = fma2(aq2, vy, acc[pr][0][1]);
            acc[pr][0][2] = fma2(aq2, vz, acc[pr][0][2]);
            acc[pr][1][0] = fma2(ak2, vx, acc[pr][1][0]);
            acc[pr][1][1] = fma2(ak2, vy, acc[pr][1][1]);
            acc[pr][1][2] = fma2(ak2, vz, acc[pr][1][2]);
            acc[pr][2][0] = fma2(au2, vx, acc[pr][2][0]);
            acc[pr][2][1] = fma2(au2, vy, acc[pr][2][1]);
            acc[pr][2][2] = fma2(au2, vz, acc[pr][2][2]);
        }
    }

    // epilogue: unpack, store, accumulate channel norms
    float nq[4], nk[4];
#pragma unroll
    for (int pr = 0; pr < 2; pr++) {
        float q0x,q1x,q0y,q1y,q0z,q1z;
        float k0x,k1x,k0y,k1y,k0z,k1z;
        float u0x,u1x,u0y,u1y,u0z,u1z;
        unpack2(acc[pr][0][0], q0x, q1x);
        unpack2(acc[pr][0][1], q0y, q1y);
        unpack2(acc[pr][0][2], q0z, q1z);
        unpack2(acc[pr][1][0], k0x, k1x);
        unpack2(acc[pr][1][1], k0y, k1y);
        unpack2(acc[pr][1][2], k0z, k1z);
        unpack2(acc[pr][2][0], u0x, u1x);
        unpack2(acc[pr][2][1], u0y, u1y);
        unpack2(acc[pr][2][2], u0z, u1z);
        size_t b0 = ((size_t)(p0 + h4 + pr*2 + 0)) * (CH*3) + o*3;
        size_t b1 = ((size_t)(p0 + h4 + pr*2 + 1)) * (CH*3) + o*3;
        g_Q[b0+0]=q0x; g_Q[b0+1]=q0y; g_Q[b0+2]=q0z;
        g_Q[b1+0]=q1x; g_Q[b1+1]=q1y; g_Q[b1+2]=q1z;
        g_K[b0+0]=k0x; g_K[b0+1]=k0y; g_K[b0+2]=k0z;
        g_K[b1+0]=k1x; g_K[b1+1]=k1y; g_K[b1+2]=k1z;
        g_U[b0+0]=u0x; g_U[b0+1]=u0y; g_U[b0+2]=u0z;
        g_U[b1+0]=u1x; g_U[b1+1]=u1y; g_U[b1+2]=u1z;
        nq[pr*2+0] = sqrtf(q0x*q0x + q0y*q0y + q0z*q0z);
        nq[pr*2+1] = sqrtf(q1x*q1x + q1y*q1y + q1z*q1z);
        nk[pr*2+0] = sqrtf(k0x*k0x + k0y*k0y + k0z*k0z);
        nk[pr*2+1] = sqrtf(k1x*k1x + k1y*k1y + k1z*k1z);
    }
#pragma unroll
    for (int t = 0; t < 4; t++) {
        float vq = nq[t], vk = nk[t];
#pragma unroll
        for (int s = 16; s > 0; s >>= 1) {
            vq += __shfl_xor_sync(0xffffffffu, vq, s);
            vk += __shfl_xor_sync(0xffffffffu, vk, s);
        }
        if (lane == 0) { swn[h][t][w4][0] = vq; swn[h][t][w4][1] = vk; }
    }
    __syncthreads();
    if (threadIdx.x < 16) {
        int h2 = threadIdx.x >> 3, t = (threadIdx.x >> 1) & 3, qk = threadIdx.x & 1;
        float s = swn[h2][t][0][qk] + swn[h2][t][1][qk]
                + swn[h2][t][2][qk] + swn[h2][t][3][qk];
        int pt = p0 + h2*4 + t;
        if (qk == 0) g_qn[pt] = s * (1.f/128.f);
        else         g_kn[pt] = s * (1.f/128.f);
    }
}

// ---------------- attention + message + vn layer norm + clamp ---------------
__global__ __launch_bounds__(128) void attn_kernel(
    const float* __restrict__ W1, const float* __restrict__ b1,
    const float* __restrict__ W2, const float* __restrict__ b2,
    const float* __restrict__ W3, const float* __restrict__ b3,
    const float* __restrict__ gamma, const float* __restrict__ beta,
    float* __restrict__ out) {
    int n = blockIdx.x;
    int tid = threadIdx.x;
    int lane = tid & 31, wid = tid >> 5;

    __shared__ float sW1t[4*HID];        // transposed [j][u]
    __shared__ float sW2t[HID*HID];      // transposed [i][u]
    __shared__ float sb1[HID], sb2[HID], sW3[HID];
    __shared__ float sqn, sb3;
    __shared__ int   sidx[KNN];
    __shared__ float skn[KNN], sdist[KNN], sdot[KNN], satt[KNN];
    __shared__ float sh1[KNN][HID+1];    // padded: conflict-free
    __shared__ float sh2[KNN][HID+1];
    __shared__ float sred[4];

    // ---- loads ----
    if (tid < 128) {                     // W1 transpose: 32x4 -> [j][u]
        int u = tid >> 2, j = tid & 3;
        sW1t[j*HID + u] = W1[tid];
    }
    for (int i = tid; i < HID*HID; i += 128) {
        int u = i >> 5, jj = i & 31;
        sW2t[jj*HID + u] = W2[i];
    }
    if (tid < HID) { sb1[tid] = b1[tid]; sb2[tid] = b2[tid]; sW3[tid] = W3[tid]; }
    if (tid == 0)  { sb3 = b3[0]; sqn = g_qn[n]; }
    if (tid < KNN) {
        int j = g_idx[n*KNN + tid];
        sidx[tid]  = j;
        skn[tid]   = g_kn[j];
        sdist[tid] = g_dist[n*KNN + tid];
    }
    __syncthreads();

    // own channel of Q (for message + residual)
    size_t qb = (size_t)n*384 + tid*3;
    float qx = g_Q[qb], qy = g_Q[qb+1], qz = g_Q[qb+2];

    // ---- dot_nbr: 16 neighbors x 8 threads; each thread sums 16 channels ----
    {
        int k = tid >> 3, g = tid & 7;
        const float4* Qp = reinterpret_cast<const float4*>(g_Q + (size_t)n*384) + g*12;
        const float4* Kp = reinterpret_cast<const float4*>(g_K + (size_t)sidx[k]*384) + g*12;
        float d = 0.f;
#pragma unroll
        for (int i = 0; i < 12; i++) {
            float4 a = Qp[i], bq = Kp[i];
            d = fmaf(a.x, bq.x, d);
            d = fmaf(a.y, bq.y, d);
            d = fmaf(a.z, bq.z, d);
            d = fmaf(a.w, bq.w, d);
        }
#pragma unroll
        for (int s = 4; s > 0; s >>= 1) d += __shfl_xor_sync(0xffffffffu, d, s);
        if (g == 0) sdot[k] = d * (1.f/128.f);
    }
    __syncthreads();

    // ---- MLP layer 1: 512 tasks over 128 threads x 4 ----
#pragma unroll
    for (int r = 0; r < 4; r++) {
        int m = tid + 128*r;
        int k = m >> 5, u = m & 31;
        float hv = sb1[u] + sW1t[0*HID+u]*sqn + sW1t[1*HID+u]*skn[k]
                          + sW1t[2*HID+u]*sdot[k] + sW1t[3*HID+u]*sdist[k];
        sh1[k][u] = hv / (1.f + expf(-hv));
    }
    __syncthreads();
    // ---- layer 2 (conflict-free W2t) ----
#pragma unroll
    for (int r = 0; r < 4; r++) {
        int m = tid + 128*r;
        int k = m >> 5, u = m & 31;
        float hv = sb2[u];
#pragma unroll
        for (int i = 0; i < HID; i++) hv = fmaf(sW2t[i*HID+u], sh1[k][i], hv);
        sh2[k][u] = hv / (1.f + expf(-hv));
    }
    __syncthreads();
    // ---- layer 3 + clip + softmax, entirely in warp 0 ----
    if (wid == 0) {
        float l = -INFINITY;
        if (lane < KNN) {
            float t = sb3;
#pragma unroll
            for (int i = 0; i < HID; i++) t = fmaf(sW3[i], sh2[lane][i], t);
            l = fminf(fmaxf(t, -10.f), 10.f);
        }
        float mx = l;
#pragma unroll
        for (int s = 8; s > 0; s >>= 1)
            mx = fmaxf(mx, __shfl_xor_sync(0xffffffffu, mx, s));
        float e = (lane < KNN) ? expf(l - mx) : 0.f;
        float sum = e;
#pragma unroll
        for (int s = 8; s > 0; s >>= 1) sum += __shfl_xor_sync(0xffffffffu, sum, s);
        if (lane < KNN) satt[lane] = e / sum;
    }
    __syncthreads();

    // ---- message ----
    float mxs = 0.f, mys = 0.f, mzs = 0.f;
#pragma unroll
    for (int k = 0; k < KNN; k++) {
        const float* Up = g_U + (size_t)sidx[k]*384 + tid*3;
        float a = satt[k];
        mxs = fmaf(a, Up[0], mxs);
        mys = fmaf(a, Up[1], mys);
        mzs = fmaf(a, Up[2], mzs);
    }
    float ox = qx + 0.5f*mxs;
    float oy = qy + 0.5f*mys;
    float oz = qz + 0.5f*mzs;

    // ---- vn layer norm ----
    float nrm = fmaxf(sqrtf(ox*ox + oy*oy + oz*oz), EPSV);
    float vv = nrm;
#pragma unroll
    for (int s = 16; s > 0; s >>= 1) vv += __shfl_xor_sync(0xffffffffu, vv, s);
    if (lane == 0) sred[wid] = vv;
    __syncthreads();
    float mean = (sred[0]+sred[1]+sred[2]+sred[3]) * (1.f/128.f);
    __syncthreads();
    float dev = nrm - mean;
    vv = dev*dev;
#pragma unroll
    for (int s = 16; s > 0; s >>= 1) vv += __shfl_xor_sync(0xffffffffu, vv, s);
    if (lane == 0) sred[wid] = vv;
    __syncthreads();
    float stdv = fmaxf(sqrtf((sred[0]+sred[1]+sred[2]+sred[3]) * (1.f/127.f)), EPSV);
    float ns = (dev/stdv)*gamma[tid] + beta[tid];
    float sc = fmaxf(ns, EPSV) / nrm;
    ox *= sc; oy *= sc; oz *= sc;

    float n2 = fmaxf(sqrtf(ox*ox + oy*oy + oz*oz), EPSV);
    float cl = fminf(50.f/n2, 1.f);
    size_t ob = (size_t)n*384 + tid*3;
    out[ob+0] = ox*cl; out[ob+1] = oy*cl; out[ob+2] = oz*cl;
}

// ---------------- launch ----------------------------------------------------
extern "C" void kernel_launch(void* const* d_in, const int* in_sizes, int n_in,
                              void* d_out, int out_size) {
    const float* x     = (const float*)d_in[0];
    const float* v     = (const float*)d_in[1];
    const float* Wq    = (const float*)d_in[2];
    const float* Wk    = (const float*)d_in[3];
    const float* Wu    = (const float*)d_in[4];
    const float* W1    = (const float*)d_in[5];
    const float* b1    = (const float*)d_in[6];
    const float* W2    = (const float*)d_in[7];
    const float* b2    = (const float*)d_in[8];
    const float* W3    = (const float*)d_in[9];
    const float* b3    = (const float*)d_in[10];
    const float* gamma = (const float*)d_in[11];
    const float* beta  = (const float*)d_in[12];
    float* out = (float*)d_out;

    transpose_w_kernel<<<64, 256>>>(Wq, Wk, Wu);
    knn_kernel<<<2048, 256>>>(x);
    gemm_kernel<<<2048, 256>>>(v);
    attn_kernel<<<NTOT, 128>>>(W1, b1, W2, b2, W3, b3, gamma, beta, out);
}

// round 3
// speedup vs baseline: 1.0444x; 1.0444x over previous
#include <cuda_runtime.h>
#include <math.h>

#define BATCH 8
#define NPTS 2048
#define NTOT (BATCH*NPTS)
#define CH 128
#define KNN 16
#define HID 32
#define EPSV 1e-6f

typedef unsigned long long ull;

// ---------------- scratch (static device globals) ---------------------------
__device__ float g_Q[NTOT*CH*3];
__device__ float g_K[NTOT*CH*3];
__device__ float g_U[NTOT*CH*3];
__device__ float g_Wt[3*CH*CH];      // transposed weights, layout [w][c][o]
__device__ int   g_idx[NTOT*KNN];    // global neighbor index (b*NPTS + j)
__device__ float g_dist[NTOT*KNN];
__device__ float g_qn[NTOT];
__device__ float g_kn[NTOT];

// ---------------- packed f32x2 helpers (Blackwell FFMA2) --------------------
__device__ __forceinline__ ull pack2(float lo, float hi) {
    ull r;
    asm("mov.b64 %0, {%1,%2};" : "=l"(r) : "f"(lo), "f"(hi));
    return r;
}
__device__ __forceinline__ void unpack2(ull v, float& lo, float& hi) {
    asm("mov.b64 {%0,%1}, %2;" : "=f"(lo), "=f"(hi) : "l"(v));
}
__device__ __forceinline__ ull fma2(ull a, ull b, ull c) {
    ull d;
    asm("fma.rn.f32x2 %0, %1, %2, %3;" : "=l"(d) : "l"(a), "l"(b), "l"(c));
    return d;
}
__device__ __forceinline__ void group_bar(int g) {
    asm volatile("bar.sync %0, 128;" :: "r"(g + 1) : "memory");
}

// ---------------- weight transpose: W[o][c] -> Wt[c][o] ----------------------
__global__ void transpose_w_kernel(const float* __restrict__ Wq,
                                   const float* __restrict__ Wk,
                                   const float* __restrict__ Wu) {
    int i = blockIdx.x * 256 + threadIdx.x;       // i = o*128 + c
    if (i >= CH*CH) return;
    int o = i >> 7, c = i & 127;
    g_Wt[0*CH*CH + c*CH + o] = Wq[i];
    g_Wt[1*CH*CH + c*CH + o] = Wk[i];
    g_Wt[2*CH*CH + c*CH + o] = Wu[i];
}

// ---------------- KNN: warp per query, per-lane sorted top-16, warp merge ---
__global__ __launch_bounds__(256) void knn_kernel(const float* __restrict__ x) {
    __shared__ float sx[NPTS*3];
    __shared__ float ssq[NPTS];
    int b  = blockIdx.x >> 8;
    int n0 = (blockIdx.x & 255) << 3;
    const float* xb = x + (size_t)b * NPTS * 3;
    for (int i = threadIdx.x; i < NPTS*3; i += 256) sx[i] = xb[i];
    __syncthreads();
    for (int i = threadIdx.x; i < NPTS; i += 256) {
        float a = sx[3*i], bb = sx[3*i+1], c = sx[3*i+2];
        ssq[i] = a*a + bb*bb + c*c;
    }
    __syncthreads();

    int warp = threadIdx.x >> 5, lane = threadIdx.x & 31;
    int n = n0 + warp;
    float qx = sx[3*n], qy = sx[3*n+1], qz = sx[3*n+2];
    float qs = ssq[n];

    float bd[KNN]; int bi[KNN];
#pragma unroll
    for (int t = 0; t < KNN; t++) { bd[t] = INFINITY; bi[t] = 0x7fffffff; }

    for (int j = lane; j < NPTS; j += 32) {
        float dot = qx*sx[3*j] + qy*sx[3*j+1] + qz*sx[3*j+2];
        float d2 = (qs + ssq[j]) - 2.f*dot;
        if (j == n) d2 = INFINITY;
        if (d2 < bd[KNN-1]) {
            bool placed = false;
#pragma unroll
            for (int t = KNN-1; t >= 1; t--) {
                if (!placed) {
                    if (d2 < bd[t-1]) { bd[t] = bd[t-1]; bi[t] = bi[t-1]; }
                    else              { bd[t] = d2;      bi[t] = j; placed = true; }
                }
            }
            if (!placed) { bd[0] = d2; bi[0] = j; }
        }
    }

    int myj = 0;
    for (int r = 0; r < KNN; r++) {
        ull key = (((ull)__float_as_uint(bd[0])) << 32) | (unsigned)bi[0];
        ull mn = key;
#pragma unroll
        for (int s = 16; s > 0; s >>= 1) {
            ull o = __shfl_xor_sync(0xffffffffu, mn, s);
            mn = (o < mn) ? o : mn;
        }
        if (lane == r) myj = (int)(unsigned)(mn & 0xffffffffu);
        if (key == mn) {
#pragma unroll
            for (int t = 0; t < KNN-1; t++) { bd[t] = bd[t+1]; bi[t] = bi[t+1]; }
            bd[KNN-1] = INFINITY; bi[KNN-1] = 0x7fffffff;
        }
    }

    if (lane < KNN) {
        int j = myj;
        float dx = qx - sx[3*j], dy = qy - sx[3*j+1], dz = qz - sx[3*j+2];
        int gi = ((b << 11) + n) * KNN + lane;
        g_idx[gi]  = (b << 11) + j;
        g_dist[gi] = sqrtf(dx*dx + dy*dy + dz*dz);
    }
}

// ---------------- fused GEMM (FFMA2 packed) + channel-norm reduction --------
__global__ __launch_bounds__(256) void gemm_kernel(const float* __restrict__ v) {
    __shared__ float svt[8*CH*3];            // [c][coord][8 points]
    __shared__ float swn[2][4][4][2];
    int p0 = blockIdx.x << 3;
    const float* vb = v + (size_t)p0 * (CH*3);
    for (int i = threadIdx.x; i < 8*CH*3; i += 256) {
        int p = i / 384, r = i % 384;
        int c = r / 3, coord = r % 3;
        svt[c*24 + coord*8 + p] = vb[i];
    }
    __syncthreads();

    int o    = threadIdx.x & 127;
    int h    = threadIdx.x >> 7;
    int lane = threadIdx.x & 31;
    int w4   = (threadIdx.x >> 5) & 3;
    int h4   = h * 4;

    ull acc[2][3][3];
#pragma unroll
    for (int pr = 0; pr < 2; pr++)
#pragma unroll
        for (int w = 0; w < 3; w++)
#pragma unroll
            for (int d = 0; d < 3; d++) acc[pr][w][d] = 0ULL;

    const float* wq = g_Wt + o;
    const float* wk = g_Wt + CH*CH + o;
    const float* wu = g_Wt + 2*CH*CH + o;

#pragma unroll 4
    for (int c = 0; c < CH; c++) {
        float aq = __ldg(wq + (c << 7));
        float ak = __ldg(wk + (c << 7));
        float au = __ldg(wu + (c << 7));
        ull aq2 = pack2(aq, aq), ak2 = pack2(ak, ak), au2 = pack2(au, au);
#pragma unroll
        for (int pr = 0; pr < 2; pr++) {
            const ull* vp = reinterpret_cast<const ull*>(&svt[c*24 + h4 + pr*2]);
            ull vx = vp[0];
            ull vy = vp[4];
            ull vz = vp[8];
            acc[pr][0][0] = fma2(aq2, vx, acc[pr][0][0]);
            acc[pr][0][1] = fma2(aq2, vy, acc[pr][0][1]);
            acc[pr][0][2] = fma2(aq2, vz, acc[pr][0][2]);
            acc[pr][1][0] = fma2(ak2, vx, acc[pr][1][0]);
            acc[pr][1][1] = fma2(ak2, vy, acc[pr][1][1]);
            acc[pr][1][2] = fma2(ak2, vz, acc[pr][1][2]);
            acc[pr][2][0] = fma2(au2, vx, acc[pr][2][0]);
            acc[pr][2][1] = fma2(au2, vy, acc[pr][2][1]);
            acc[pr][2][2] = fma2(au2, vz, acc[pr][2][2]);
        }
    }

    float nq[4], nk[4];
#pragma unroll
    for (int pr = 0; pr < 2; pr++) {
        float q0x,q1x,q0y,q1y,q0z,q1z;
        float k0x,k1x,k0y,k1y,k0z,k1z;
        float u0x,u1x,u0y,u1y,u0z,u1z;
        unpack2(acc[pr][0][0], q0x, q1x);
        unpack2(acc[pr][0][1], q0y, q1y);
        unpack2(acc[pr][0][2], q0z, q1z);
        unpack2(acc[pr][1][0], k0x, k1x);
        unpack2(acc[pr][1][1], k0y, k1y);
        unpack2(acc[pr][1][2], k0z, k1z);
        unpack2(acc[pr][2][0], u0x, u1x);
        unpack2(acc[pr][2][1], u0y, u1y);
        unpack2(acc[pr][2][2], u0z, u1z);
        size_t b0 = ((size_t)(p0 + h4 + pr*2 + 0)) * (CH*3) + o*3;
        size_t b1 = ((size_t)(p0 + h4 + pr*2 + 1)) * (CH*3) + o*3;
        g_Q[b0+0]=q0x; g_Q[b0+1]=q0y; g_Q[b0+2]=q0z;
        g_Q[b1+0]=q1x; g_Q[b1+1]=q1y; g_Q[b1+2]=q1z;
        g_K[b0+0]=k0x; g_K[b0+1]=k0y; g_K[b0+2]=k0z;
        g_K[b1+0]=k1x; g_K[b1+1]=k1y; g_K[b1+2]=k1z;
        g_U[b0+0]=u0x; g_U[b0+1]=u0y; g_U[b0+2]=u0z;
        g_U[b1+0]=u1x; g_U[b1+1]=u1y; g_U[b1+2]=u1z;
        nq[pr*2+0] = sqrtf(q0x*q0x + q0y*q0y + q0z*q0z);
        nq[pr*2+1] = sqrtf(q1x*q1x + q1y*q1y + q1z*q1z);
        nk[pr*2+0] = sqrtf(k0x*k0x + k0y*k0y + k0z*k0z);
        nk[pr*2+1] = sqrtf(k1x*k1x + k1y*k1y + k1z*k1z);
    }
#pragma unroll
    for (int t = 0; t < 4; t++) {
        float vq = nq[t], vk = nk[t];
#pragma unroll
        for (int s = 16; s > 0; s >>= 1) {
            vq += __shfl_xor_sync(0xffffffffu, vq, s);
            vk += __shfl_xor_sync(0xffffffffu, vk, s);
        }
        if (lane == 0) { swn[h][t][w4][0] = vq; swn[h][t][w4][1] = vk; }
    }
    __syncthreads();
    if (threadIdx.x < 16) {
        int h2 = threadIdx.x >> 3, t = (threadIdx.x >> 1) & 3, qk = threadIdx.x & 1;
        float s = swn[h2][t][0][qk] + swn[h2][t][1][qk]
                + swn[h2][t][2][qk] + swn[h2][t][3][qk];
        int pt = p0 + h2*4 + t;
        if (qk == 0) g_qn[pt] = s * (1.f/128.f);
        else         g_kn[pt] = s * (1.f/128.f);
    }
}

// ---------------- fused attention: 4 points/block, named-barrier groups -----
__global__ __launch_bounds__(512) void attn_kernel(
    const float* __restrict__ W1, const float* __restrict__ b1,
    const float* __restrict__ W2, const float* __restrict__ b2,
    const float* __restrict__ W3, const float* __restrict__ b3,
    const float* __restrict__ gamma, const float* __restrict__ beta,
    float* __restrict__ out) {
    int tid  = threadIdx.x;
    int g    = tid >> 7;          // point group 0..3
    int gtid = tid & 127;         // thread within group
    int lane = tid & 31;
    int gw   = (tid >> 5) & 3;    // warp within group
    int n    = (blockIdx.x << 2) + g;

    __shared__ float sW1t[4*HID];
    __shared__ float sW2t[HID*HID];
    __shared__ float sb1[HID], sb2[HID], sW3[HID];
    __shared__ float sb3;
    __shared__ int   sidx[4][KNN];
    __shared__ float skn[4][KNN], sdist[4][KNN], sdot[4][KNN], satt[4][KNN];
    __shared__ float sqn[4];
    __shared__ float sh1[4][KNN][HID+1];
    __shared__ float sh2[4][KNN][HID+1];
    __shared__ float sred[4][4];

    // ---- global loads (block-wide weights + per-group edge data) ----
    if (tid < 128) {                     // W1 transpose: 32x4 -> [j][u]
        int u = tid >> 2, j = tid & 3;
        sW1t[j*HID + u] = W1[tid];
    }
    for (int i = tid; i < HID*HID; i += 512) {
        int u = i >> 5, jj = i & 31;
        sW2t[jj*HID + u] = W2[i];
    }
    if (tid < HID && tid >= 0) { sb1[tid] = b1[tid]; sb2[tid] = b2[tid]; sW3[tid] = W3[tid]; }
    if (tid == 0) sb3 = b3[0];
    if (gtid == 0) sqn[g] = g_qn[n];
    if (gtid < KNN) {
        int j = g_idx[n*KNN + gtid];
        sidx[g][gtid]  = j;
        skn[g][gtid]   = g_kn[j];
        sdist[g][gtid] = g_dist[n*KNN + gtid];
    }
    __syncthreads();

    // own channel of Q (for message + residual)
    int ch = gtid;
    size_t qb = (size_t)n*384 + ch*3;
    float qx = g_Q[qb], qy = g_Q[qb+1], qz = g_Q[qb+2];

    // ---- dot_nbr: 16 neighbors x 8 threads, float4 coalesced ----
    {
        int k = gtid >> 3, gg = gtid & 7;
        const float4* Qp = reinterpret_cast<const float4*>(g_Q + (size_t)n*384) + gg*12;
        const float4* Kp = reinterpret_cast<const float4*>(g_K + (size_t)sidx[g][k]*384) + gg*12;
        float d = 0.f;
#pragma unroll
        for (int i = 0; i < 12; i++) {
            float4 a = Qp[i], bq = Kp[i];
            d = fmaf(a.x, bq.x, d);
            d = fmaf(a.y, bq.y, d);
            d = fmaf(a.z, bq.z, d);
            d = fmaf(a.w, bq.w, d);
        }
#pragma unroll
        for (int s = 4; s > 0; s >>= 1) d += __shfl_xor_sync(0xffffffffu, d, s);
        if (gg == 0) sdot[g][k] = d * (1.f/128.f);
    }
    group_bar(g);

    // ---- MLP layer 1: 512 tasks per point over 128 threads x 4 ----
#pragma unroll
    for (int r = 0; r < 4; r++) {
        int m = gtid + 128*r;
        int k = m >> 5, u = m & 31;
        float hv = sb1[u] + sW1t[0*HID+u]*sqn[g] + sW1t[1*HID+u]*skn[g][k]
                          + sW1t[2*HID+u]*sdot[g][k] + sW1t[3*HID+u]*sdist[g][k];
        sh1[g][k][u] = hv / (1.f + expf(-hv));
    }
    group_bar(g);
    // ---- layer 2 ----
#pragma unroll
    for (int r = 0; r < 4; r++) {
        int m = gtid + 128*r;
        int k = m >> 5, u = m & 31;
        float hv = sb2[u];
#pragma unroll
        for (int i = 0; i < HID; i++) hv = fmaf(sW2t[i*HID+u], sh1[g][k][i], hv);
        sh2[g][k][u] = hv / (1.f + expf(-hv));
    }
    group_bar(g);
    // ---- layer 3 + clip + softmax in group's warp 0 ----
    if (gw == 0) {
        float l = -INFINITY;
        if (lane < KNN) {
            float t = sb3;
#pragma unroll
            for (int i = 0; i < HID; i++) t = fmaf(sW3[i], sh2[g][lane][i], t);
            l = fminf(fmaxf(t, -10.f), 10.f);
        }
        float mx = l;
#pragma unroll
        for (int s = 8; s > 0; s >>= 1)
            mx = fmaxf(mx, __shfl_xor_sync(0xffffffffu, mx, s));
        float e = (lane < KNN) ? expf(l - mx) : 0.f;
        float sum = e;
#pragma unroll
        for (int s = 8; s > 0; s >>= 1) sum += __shfl_xor_sync(0xffffffffu, sum, s);
        if (lane < KNN) satt[g][lane] = e / sum;
    }
    group_bar(g);

    // ---- message ----
    float mxs = 0.f, mys = 0.f, mzs = 0.f;
#pragma unroll
    for (int k = 0; k < KNN; k++) {
        const float* Up = g_U + (size_t)sidx[g][k]*384 + ch*3;
        float a = satt[g][k];
        mxs = fmaf(a, Up[0], mxs);
        mys = fmaf(a, Up[1], mys);
        mzs = fmaf(a, Up[2], mzs);
    }
    float ox = qx + 0.5f*mxs;
    float oy = qy + 0.5f*mys;
    float oz = qz + 0.5f*mzs;

    // ---- vn layer norm (group-scope reduce) ----
    float nrm = fmaxf(sqrtf(ox*ox + oy*oy + oz*oz), EPSV);
    float vv = nrm;
#pragma unroll
    for (int s = 16; s > 0; s >>= 1) vv += __shfl_xor_sync(0xffffffffu, vv, s);
    if (lane == 0) sred[g][gw] = vv;
    group_bar(g);
    float mean = (sred[g][0]+sred[g][1]+sred[g][2]+sred[g][3]) * (1.f/128.f);
    group_bar(g);
    float dev = nrm - mean;
    vv = dev*dev;
#pragma unroll
    for (int s = 16; s > 0; s >>= 1) vv += __shfl_xor_sync(0xffffffffu, vv, s);
    if (lane == 0) sred[g][gw] = vv;
    group_bar(g);
    float stdv = fmaxf(sqrtf((sred[g][0]+sred[g][1]+sred[g][2]+sred[g][3]) * (1.f/127.f)), EPSV);
    float ns = (dev/stdv)*gamma[ch] + beta[ch];
    float sc = fmaxf(ns, EPSV) / nrm;
    ox *= sc; oy *= sc; oz *= sc;

    float n2 = fmaxf(sqrtf(ox*ox + oy*oy + oz*oz), EPSV);
    float cl = fminf(50.f/n2, 1.f);
    size_t ob = (size_t)n*384 + ch*3;
    out[ob+0] = ox*cl; out[ob+1] = oy*cl; out[ob+2] = oz*cl;
}

// ---------------- launch ----------------------------------------------------
extern "C" void kernel_launch(void* const* d_in, const int* in_sizes, int n_in,
                              void* d_out, int out_size) {
    const float* x     = (const float*)d_in[0];
    const float* v     = (const float*)d_in[1];
    const float* Wq    = (const float*)d_in[2];
    const float* Wk    = (const float*)d_in[3];
    const float* Wu    = (const float*)d_in[4];
    const float* W1    = (const float*)d_in[5];
    const float* b1    = (const float*)d_in[6];
    const float* W2    = (const float*)d_in[7];
    const float* b2    = (const float*)d_in[8];
    const float* W3    = (const float*)d_in[9];
    const float* b3    = (const float*)d_in[10];
    const float* gamma = (const float*)d_in[11];
    const float* beta  = (const float*)d_in[12];
    float* out = (float*)d_out;

    transpose_w_kernel<<<64, 256>>>(Wq, Wk, Wu);
    knn_kernel<<<2048, 256>>>(x);
    gemm_kernel<<<2048, 256>>>(v);
    attn_kernel<<<NTOT/4, 512>>>(W1, b1, W2, b2, W3, b3, gamma, beta, out);
}